// round 5
// baseline (speedup 1.0000x reference)
#include <cuda_runtime.h>
#include <cuda_bf16.h>

// FWHT-4096 / sqrt(4096). Index i = A*256 + B*16 + C (A,B,C in [0,16)).
// Round 1: H16 over A (bits 8..11) in regs — loads fully coalesced (lanes = B*16+C)
// Round 2: H16 over B (bits 4..7)  in regs — via swizzled smem, conflict-free
// Round 3: H16 over C (bits 0..3)  in regs — float4 stores, fully coalesced
// Hadamard bit-stages commute, so this equals the reference 12-stage FWHT.
//
// Swizzled packed smem layout (bijective onto [0,4096), no padding):
//   phys(A,B,C) = (A*8 + (B>>1))*32 + 16*((A^B)&1) + (C ^ ((4A+B)&15))
// Conflict-free for all four passes:
//   W1  lanes (B in {b0,b0+1}, C all): parity bit splits halves, C^q fills each
//   R2/W2 lanes (A in {a0,a0+1}, C all): same argument via A-parity
//   R3  lanes (A in {a0,a0+1}, B all): q = (4A+B)&15 gives disjoint even/odd
//       q-images across the A pair -> each 16-bank half fully covered

#define FWHT_N 4096
#define FWHT_T 256

__device__ __forceinline__ int sw_phys(int A, int B, int C) {
    return ((A << 3) + (B >> 1)) * 32 + (((A ^ B) & 1) << 4) + (C ^ ((4 * A + B) & 15));
}

__device__ __forceinline__ void h16(float v[16]) {
#pragma unroll
    for (int h = 1; h < 16; h <<= 1) {
#pragma unroll
        for (int i = 0; i < 16; i++) {
            if (!(i & h)) {
                float a = v[i], b = v[i | h];
                v[i]     = a + b;
                v[i | h] = a - b;
            }
        }
    }
}

__global__ void __launch_bounds__(FWHT_T, 6)
fwht4096_kernel(const float* __restrict__ x, float* __restrict__ out) {
    __shared__ float s[FWHT_N];

    const int j = threadIdx.x;
    const size_t row = blockIdx.x;
    const float* __restrict__ xr = x + row * FWHT_N;
    float* __restrict__ orow     = out + row * FWHT_N;

    float v[16];

    // ---- Round 1: regs = A. Lanes = j = B*16+C -> each LDG.32 warp = one 128B line.
#pragma unroll
    for (int A = 0; A < 16; A++) v[A] = xr[A * 256 + j];
    h16(v);   // transforms bits 8..11

    // W1: thread (B,C) scatters its A-vector into swizzled smem.
    {
        const int B = j >> 4, C = j & 15;
#pragma unroll
        for (int A = 0; A < 16; A++) s[sw_phys(A, B, C)] = v[A];
    }
    __syncthreads();

    // ---- Round 2: thread (A,C) owns all (A,*,C); regs = B. No barrier inside:
    // ownership across threads is disjoint (phys is bijective).
    {
        const int A = j >> 4, C = j & 15;
#pragma unroll
        for (int B = 0; B < 16; B++) v[B] = s[sw_phys(A, B, C)];
        h16(v);   // transforms bits 4..7
#pragma unroll
        for (int B = 0; B < 16; B++) s[sw_phys(A, B, C)] = v[B];
    }
    __syncthreads();

    // ---- Round 3: thread (A,B); regs = C. Then float4 stores.
    {
        const int A = j >> 4, B = j & 15;
        const int base = ((A << 3) + (B >> 1)) * 32 + (((A ^ B) & 1) << 4);
        const int q = (4 * A + B) & 15;
#pragma unroll
        for (int C = 0; C < 16; C++) v[C] = s[base + (C ^ q)];
        h16(v);   // transforms bits 0..3

        const float scale = 1.0f / 64.0f;   // 1/sqrt(4096)
        float4* __restrict__ o = reinterpret_cast<float4*>(orow + A * 256 + B * 16);
        // Warp = 2 A-values x 16 B-values -> two 256B contiguous chunks per STG.128.
#pragma unroll
        for (int c4 = 0; c4 < 4; c4++) {
            float4 t;
            t.x = v[4 * c4 + 0] * scale;
            t.y = v[4 * c4 + 1] * scale;
            t.z = v[4 * c4 + 2] * scale;
            t.w = v[4 * c4 + 3] * scale;
            o[c4] = t;
        }
    }
}

extern "C" void kernel_launch(void* const* d_in, const int* in_sizes, int n_in,
                              void* d_out, int out_size) {
    const float* x = (const float*)d_in[0];
    float* out     = (float*)d_out;
    const int nrows = in_sizes[0] / FWHT_N;   // 16384
    fwht4096_kernel<<<nrows, FWHT_T>>>(x, out);
}

// round 7
// speedup vs baseline: 1.2499x; 1.2499x over previous
#include <cuda_runtime.h>
#include <cuda_bf16.h>

// FWHT-4096 / sqrt(4096). R4 schedule (proven conflict-free, cheap affine
// addressing) + persistent CTAs with register prefetch of the next row so the
// DRAM read stream never drains during the smem/FADD phases.
//
// Index i = Q*1024 + P*128 + D*32 + L  (Q:2b i[10:12], P:3b i[7:10],
//                                       D:2b i[5:7],  L:5b i[0:5])
// Round 1: H32 over (Q,P)=i[7:12] in regs  (loads: lanes = j, ideal coalescing)
// Round 2: H32 over L=i[0:5]      in regs  (smem transpose, conflict-free)
// Round 3: H4  over D=i[5:7]      in regs  (stores: lanes = L, ideal coalescing)
// Hadamard bit-stages commute -> equals the reference 12-stage FWHT.

#define FWHT_N 4096
#define ROW_THREADS 128
#define GRID_CTAS 760            // ~5 CTAs/SM x 152 SMs, all-resident persistent
// smem strides: L:1, D:33 (==1 mod 32), P:132 (==4 mod 32), Q:1056 (==0 mod 32)
#define S_D 33
#define S_P 132
#define S_Q 1056
#define T_FLOATS (4 * S_Q)       // 4224 floats = 16.9 KB

__device__ __forceinline__ void h32(float v[32]) {
#pragma unroll
    for (int h = 1; h < 32; h <<= 1) {
#pragma unroll
        for (int i = 0; i < 32; i++) {
            if (!(i & h)) {
                float a = v[i], b = v[i | h];
                v[i]     = a + b;
                v[i | h] = a - b;
            }
        }
    }
}

__global__ void __launch_bounds__(ROW_THREADS, 5)
fwht4096_kernel(const float* __restrict__ x, float* __restrict__ out, int nrows) {
    __shared__ float T[T_FLOATS];

    const int j = threadIdx.x;
    const int stride = gridDim.x;

    // Per-thread roles (constant across rows)
    const int D1 = j >> 5, L1 = j & 31;                    // W1: thread (D,L)
    const int D2 = j & 3, P2 = (j >> 2) & 7, Q2 = j >> 5;  // R2: thread (Q,P,D)
    const int L3 = j & 31, Q3 = j >> 5;                    // R3: thread (Q,L)

    float* __restrict__ w1       = T + D1 * S_D + L1;
    float* __restrict__ b2       = T + Q2 * S_Q + P2 * S_P + D2 * S_D;
    const float* __restrict__ b3 = T + Q3 * S_Q + L3;

    int row = blockIdx.x;
    if (row >= nrows) return;

    float v[32];
    {
        const float* __restrict__ xr = x + (size_t)row * FWHT_N + j;
#pragma unroll
        for (int r = 0; r < 32; r++) v[r] = xr[r * 128];
    }

    while (true) {
        const int nrow = row + stride;
        const bool pf = (nrow < nrows);

        // ---- Round 1: H32 over regs (bits 7..11), scatter into smem ----
        h32(v);
#pragma unroll
        for (int r = 0; r < 32; r++) {
            const int Q = r >> 3, P = r & 7;
            w1[Q * S_Q + P * S_P] = v[r];   // lanes vary L -> conflict-free
        }

        // ---- Prefetch next row's 32 loads (fly during rounds 2-3 + store) ----
        float p[32];
        if (pf) {
            const float* __restrict__ xn = x + (size_t)nrow * FWHT_N + j;
#pragma unroll
            for (int r = 0; r < 32; r++) p[r] = xn[r * 128];
        }
        __syncthreads();

        // ---- Round 2: H32 over L (bits 0..4), in-place on own slots ----
        float t[32];
#pragma unroll
        for (int L = 0; L < 32; L++) t[L] = b2[L];   // banks 4P+D+L: conflict-free
        h32(t);
#pragma unroll
        for (int L = 0; L < 32; L++) b2[L] = t[L];
        __syncthreads();

        // ---- Round 3: gather (P,D), H4 over D (bits 5..6), coalesced stores ----
#pragma unroll
        for (int r = 0; r < 32; r++) {
            const int P = r >> 2, D = r & 3;
            t[r] = b3[P * S_P + D * S_D];            // lanes vary L -> conflict-free
        }
#pragma unroll
        for (int h = 1; h < 4; h <<= 1) {
#pragma unroll
            for (int i = 0; i < 32; i++) {
                if (!(i & h)) {
                    float a = t[i], c = t[i | h];
                    t[i]     = a + c;
                    t[i | h] = a - c;
                }
            }
        }
        {
            const float scale = 1.0f / 64.0f;        // 1/sqrt(4096)
            float* __restrict__ o = out + (size_t)row * FWHT_N + Q3 * 1024 + L3;
#pragma unroll
            for (int r = 0; r < 32; r++) {
                const int P = r >> 2, D = r & 3;
                o[P * 128 + D * 32] = t[r] * scale;  // lanes = L -> coalesced
            }
        }

        if (!pf) break;
        row = nrow;
#pragma unroll
        for (int r = 0; r < 32; r++) v[r] = p[r];    // register rename
        __syncthreads();   // R3 reads of T done before next row's W1 writes
    }
}

extern "C" void kernel_launch(void* const* d_in, const int* in_sizes, int n_in,
                              void* d_out, int out_size) {
    const float* x = (const float*)d_in[0];
    float* out     = (float*)d_out;
    const int nrows = in_sizes[0] / FWHT_N;          // 16384
    const int grid  = (nrows < GRID_CTAS) ? nrows : GRID_CTAS;
    fwht4096_kernel<<<grid, ROW_THREADS>>>(x, out, nrows);
}